// round 16
// baseline (speedup 1.0000x reference)
#include <cuda_runtime.h>
#include <cuda_bf16.h>
#include <cstdint>
#include <cstddef>

// Problem dims (fixed by the reference)
#define BB   64
#define TT   4096
#define DE   512
#define DA   256

// ---------------- scratch (device globals; no allocation in kernel_launch) ----------------
__device__ __nv_bfloat16 g_wk_bf[DA * DE];                  // 256 KB
__device__ float         g_qpk[BB * DA];                    // q + Wq_b + Wk_b
__device__ float         g_scores[(size_t)BB * TT];         // full additive scores
__device__ float         g_ctx_part[8][(size_t)BB * DE];    // T-split partial ctx
__device__ float         g_psum[8][BB];                     // T-split partial exp-sums

// ---------------- PTX helpers (compute_103-safe: no tcgen05/TMEM) ----------------
__device__ __forceinline__ uint32_t smem_u32(const void* p) {
    uint32_t a;
    asm("{ .reg .u64 t; cvta.to.shared.u64 t, %1; cvt.u32.u64 %0, t; }" : "=r"(a) : "l"(p));
    return a;
}
__device__ __forceinline__ void cp_async16(uint32_t dst, const void* src) {
    asm volatile("cp.async.cg.shared.global [%0], [%1], 16;" :: "r"(dst), "l"(src) : "memory");
}
__device__ __forceinline__ void cp_commit() {
    asm volatile("cp.async.commit_group;" ::: "memory");
}
template <int N>
__device__ __forceinline__ void cp_wait() {
    asm volatile("cp.async.wait_group %0;" :: "n"(N) : "memory");
}
__device__ __forceinline__ void ldmatrix_x4(uint32_t* r, uint32_t addr) {
    asm volatile("ldmatrix.sync.aligned.m8n8.x4.shared.b16 {%0,%1,%2,%3}, [%4];"
                 : "=r"(r[0]), "=r"(r[1]), "=r"(r[2]), "=r"(r[3]) : "r"(addr));
}
__device__ __forceinline__ void ldmatrix_x2(uint32_t* r, uint32_t addr) {
    asm volatile("ldmatrix.sync.aligned.m8n8.x2.shared.b16 {%0,%1}, [%2];"
                 : "=r"(r[0]), "=r"(r[1]) : "r"(addr));
}
__device__ __forceinline__ void mma16816(float* c, const uint32_t* a, const uint32_t* b) {
    asm volatile(
        "mma.sync.aligned.m16n8k16.row.col.f32.bf16.bf16.f32 "
        "{%0,%1,%2,%3}, {%4,%5,%6,%7}, {%8,%9}, {%0,%1,%2,%3};"
        : "+f"(c[0]), "+f"(c[1]), "+f"(c[2]), "+f"(c[3])
        : "r"(a[0]), "r"(a[1]), "r"(a[2]), "r"(a[3]), "r"(b[0]), "r"(b[1]));
}
__device__ __forceinline__ float tanh_approx(float x) {
    float y;
    asm("tanh.approx.f32 %0, %1;" : "=f"(y) : "f"(x));
    return y;
}
__device__ __forceinline__ uint32_t pack_bf16x2(float lo, float hi) {
    __nv_bfloat162 p = __floats2bfloat162_rn(lo, hi);
    return *reinterpret_cast<uint32_t*>(&p);
}

// SW128 swizzle (Swizzle<3,4,3>) on tile-local byte offsets, rows = 128B.
#define SWZ(o) ((o) ^ (((o) >> 3) & 0x70))

// ---------------- kernel 1: f32 -> bf16 convert (Wk only) ----------------
__global__ void convert_kernel(const float* __restrict__ src, __nv_bfloat16* __restrict__ dst, long n4) {
    long i = (long)blockIdx.x * blockDim.x + threadIdx.x;
    if (i >= n4) return;
    float4 v = reinterpret_cast<const float4*>(src)[i];
    uint2 o;
    o.x = pack_bf16x2(v.x, v.y);
    o.y = pack_bf16x2(v.z, v.w);
    reinterpret_cast<uint2*>(dst)[i] = o;
}

// ---------------- kernel 2: qpk[b,a] = h_dec[b]·Wq[a] + Wq_b[a] + Wk_b[a] ----------------
__global__ void qpk_kernel(const float* __restrict__ hdec, const float* __restrict__ Wq,
                           const float* __restrict__ Wqb, const float* __restrict__ Wkb,
                           float* __restrict__ qpk) {
    int b = blockIdx.x;
    int a = threadIdx.x;  // 256
    __shared__ float h[DE];
    for (int e = threadIdx.x; e < DE; e += 256) h[e] = hdec[b * DE + e];
    __syncthreads();
    const float* w = Wq + (size_t)a * DE;
    float acc = 0.f;
#pragma unroll 8
    for (int e = 0; e < DE; e++) acc = fmaf(h[e], w[e], acc);
    qpk[b * DA + a] = acc + Wqb[a] + Wkb[a];
}

// ---------------- kernel 3: mma.sync GEMM (M=128,N=256) + fused A-convert, MEGA-CHUNK K=128 ----------------
// 512 threads = 16 warps = 2(M) x 8(N). K=512 in 4 mega-chunks of 128 (two 64-k blocks each;
// per-block layout/swizzle identical to before). Barriers per tile: 4 instead of 8; B prefetch
// distance = 8 MMA k-steps. A staged in two ldg4/sts4 batches around the MMA loop.
#define SM_PART   0                               // float s_part[8][128] = 4096 B
#define SM_V      4096                            // float sv[256]
#define SM_Q      5120                            // float sq[256]
#define SM_A(st)  (6144 + (st) * 32768)           // A mega-stage: 2 blocks x (128 rows x 128 B)
#define SM_B(st)  (71680 + (st) * 65536)          // B mega-stage: 2 blocks x (256 rows x 128 B)
#define GEMM_SMEM 202752

__global__ void __launch_bounds__(512, 1) gemm_score_kernel(
    const float* __restrict__ A,            // [B*T, 512] f32 (h_enc)
    const __nv_bfloat16* __restrict__ Bm,   // [256, 512] bf16 (Wk)
    const float* __restrict__ qpk,
    const float* __restrict__ v_w,
    float* __restrict__ scores) {           // [B*T]
    extern __shared__ char smem[];
    uint32_t sb = smem_u32(smem);
    int tid = threadIdx.x;
    int wid = tid >> 5, lane = tid & 31;
    int wm = wid >> 3, wn = wid & 7;
    int g = lane >> 2, tig = lane & 3;

    int bx = blockIdx.x;                   // b*32 + mt
    int b  = bx >> 5;
    int t0 = (bx & 31) << 7;
    size_t m0 = (size_t)bx * 128;

    if (tid < 256) {
        ((float*)(smem + SM_V))[tid] = v_w[tid];
        ((float*)(smem + SM_Q))[tid] = qpk[b * DA + tid];
    }

    const float* Abase = A + m0 * DE;

    // A geometry per 64-k block: 128 rows x 16 float4; 512 threads x 4 each.
    int arow0 = tid >> 4;                  // 0..31
    int acol4 = tid & 15;
    uint32_t asw[4];
#pragma unroll
    for (int i = 0; i < 4; i++)
        asw[i] = (uint32_t)SWZ((arow0 + i * 32) * 128 + acol4 * 8);

    // load 64-k chunk c (global chunk index 0..7) into registers
    auto ldgA4 = [&](int c, float4* st) {
        const float4* src = (const float4*)(Abase + (size_t)c * 64);
#pragma unroll
        for (int i = 0; i < 4; i++) {
            int row = arow0 + i * 32;
            st[i] = src[(size_t)row * 128 + acol4];
        }
    };
    // store into block j (0/1) of A mega-stage stg
    auto stsA4 = [&](int stg, int j, const float4* st) {
        char* dst = smem + SM_A(stg) + j * 16384;
#pragma unroll
        for (int i = 0; i < 4; i++) {
            uint2 o;
            o.x = pack_bf16x2(st[i].x, st[i].y);
            o.y = pack_bf16x2(st[i].z, st[i].w);
            *reinterpret_cast<uint2*>(dst + asw[i]) = o;
        }
    };
    // B mega-chunk m (k cols [m*128, m*128+128)) into stage stg: 2 blocks x 2048 16B lines.
    auto issueB = [&](int m, int stg) {
        uint32_t bS = sb + SM_B(stg);
#pragma unroll
        for (int j = 0; j < 2; j++) {
            const __nv_bfloat16* bb = Bm + (m * 2 + j) * 64;
            uint32_t blk = bS + j * 32768;
#pragma unroll
            for (int i = 0; i < 4; i++) {
                int c = tid + i * 512;
                int row = c >> 3, cc = c & 7;
                cp_async16(blk + SWZ(row * 128 + cc * 16), bb + (size_t)row * DE + cc * 8);
            }
        }
        cp_commit();
    };

    float acc[4][4][4];
#pragma unroll
    for (int mi = 0; mi < 4; mi++)
#pragma unroll
        for (int ni = 0; ni < 4; ni++)
#pragma unroll
            for (int e = 0; e < 4; e++) acc[mi][ni][e] = 0.f;

    int arow = wm * 64 + (lane & 15);
    int acb  = lane >> 4;
    int brow = wn * 32 + (lane & 7);
    int bkb  = (lane >> 3) & 1;

    // ---- prologue: mega-stage 0 staged ----
    {
        issueB(0, 0);
        float4 st[4];
        ldgA4(0, st); stsA4(0, 0, st);
        ldgA4(1, st); stsA4(0, 1, st);
    }

#pragma unroll 1
    for (int mc = 0; mc < 4; mc++) {
        int cur = mc & 1, nxt = cur ^ 1;
        float4 st[4];
        if (mc < 3) ldgA4(2 * mc + 2, st); // batch 0 LDG pre-wait (register-only)
        cp_wait<0>();                       // drain B(cur)
        __syncthreads();                    // publish A/B(cur); reads of nxt retired
        if (mc < 3) issueB(mc + 1, nxt);    // safe post-sync

        uint32_t aS = sb + SM_A(cur), bS = sb + SM_B(cur);
#pragma unroll
        for (int ks = 0; ks < 4; ks++) {
            uint32_t af[4][4], bf_[4][2];
#pragma unroll
            for (int mi = 0; mi < 4; mi++)
                ldmatrix_x4(af[mi], aS + SWZ((arow + mi * 16) * 128 + ks * 32 + acb * 16));
#pragma unroll
            for (int ni = 0; ni < 4; ni++)
                ldmatrix_x2(bf_[ni], bS + SWZ((brow + ni * 8) * 128 + ks * 32 + bkb * 16));
#pragma unroll
            for (int mi = 0; mi < 4; mi++)
#pragma unroll
                for (int ni = 0; ni < 4; ni++)
                    mma16816(acc[mi][ni], af[mi], bf_[ni]);
        }
        if (mc < 3) {
            stsA4(nxt, 0, st);              // store batch 0 into nxt
            ldgA4(2 * mc + 3, st);          // batch 1 LDG, covered by second half
        }
#pragma unroll
        for (int ks = 4; ks < 8; ks++) {
            int kk = ks & 3;
            uint32_t af[4][4], bf_[4][2];
#pragma unroll
            for (int mi = 0; mi < 4; mi++)
                ldmatrix_x4(af[mi], aS + 16384 + SWZ((arow + mi * 16) * 128 + kk * 32 + acb * 16));
#pragma unroll
            for (int ni = 0; ni < 4; ni++)
                ldmatrix_x2(bf_[ni], bS + 32768 + SWZ((brow + ni * 8) * 128 + kk * 32 + bkb * 16));
#pragma unroll
            for (int mi = 0; mi < 4; mi++)
#pragma unroll
                for (int ni = 0; ni < 4; ni++)
                    mma16816(acc[mi][ni], af[mi], bf_[ni]);
        }
        if (mc < 3)
            stsA4(nxt, 1, st);              // batch 1; published by next iteration's sync
    }
    __syncthreads();                         // retire MMA smem reads before s_part reuse

    // ---- epilogue: score = sum over all 256 a of v*tanh(qpk + k) ----
    const float* sv = (const float*)(smem + SM_V);
    const float* sq = (const float*)(smem + SM_Q);
    float* s_part = (float*)(smem + SM_PART);

#pragma unroll
    for (int mi = 0; mi < 4; mi++) {
        float plo = 0.f, phi = 0.f;
#pragma unroll
        for (int ni = 0; ni < 4; ni++) {
            int n = wn * 32 + ni * 8 + tig * 2;
            float v0 = sv[n], v1 = sv[n + 1], q0 = sq[n], q1 = sq[n + 1];
            plo = fmaf(v0, tanh_approx(q0 + acc[mi][ni][0]), plo);
            plo = fmaf(v1, tanh_approx(q1 + acc[mi][ni][1]), plo);
            phi = fmaf(v0, tanh_approx(q0 + acc[mi][ni][2]), phi);
            phi = fmaf(v1, tanh_approx(q1 + acc[mi][ni][3]), phi);
        }
        plo += __shfl_xor_sync(~0u, plo, 1);
        plo += __shfl_xor_sync(~0u, plo, 2);
        phi += __shfl_xor_sync(~0u, phi, 1);
        phi += __shfl_xor_sync(~0u, phi, 2);
        if (tig == 0) {
            int row = wm * 64 + mi * 16 + g;
            s_part[wn * 128 + row] = plo;
            s_part[wn * 128 + row + 8] = phi;
        }
    }
    __syncthreads();
    if (tid < 128) {
        float s = 0.f;
#pragma unroll
        for (int j = 0; j < 8; j++) s += s_part[j * 128 + tid];
        scores[(size_t)b * TT + t0 + tid] = s;
    }
}

// ---------------- kernel 4: fused exp/mask + partial ctx over T-chunks (R12 version) ----------------
// grid (2, BB, 8): block covers 256 e-columns x 512 timesteps.
__global__ void ctx_part_kernel(const float* __restrict__ henc, const float* __restrict__ sc,
                                const void* __restrict__ maskp,
                                float* __restrict__ w, float* __restrict__ part,
                                float* __restrict__ psum) {
    int b = blockIdx.y;
    int tc = blockIdx.z;
    int e = blockIdx.x * 256 + threadIdx.x;
    int tid = threadIdx.x;
    __shared__ float ws[512];
    __shared__ float red[8];
    __shared__ int is_i32_sh;

    if (tid == 0) {
        // mask dtype auto-detect: int32 0/1 vs 1-byte bool (see R5 note)
        const uint32_t* mw = (const uint32_t*)maskp;
        int ok = 1;
        for (int i = 0; i < 64; i++)
            if (mw[i] > 1u) { ok = 0; break; }
        is_i32_sh = ok;
    }
    __syncthreads();
    int is_i32 = is_i32_sh;
    const int* mi32 = (const int*)maskp;
    const unsigned char* mu8 = (const unsigned char*)maskp;

    const float* s0 = sc + (size_t)b * TT + tc * 512;
    float local = 0.f;
    for (int t = tid; t < 512; t += 256) {
        size_t idx = (size_t)b * TT + tc * 512 + t;
        bool mv = is_i32 ? (mi32[idx] != 0) : (mu8[idx] != 0);
        float p = mv ? __expf(s0[t]) : 0.f;
        ws[t] = p;
        local += p;
    }
    __syncthreads();

    if (blockIdx.x == 0) {
        for (int t = tid; t < 512; t += 256) w[(size_t)b * TT + tc * 512 + t] = ws[t];
#pragma unroll
        for (int o = 16; o; o >>= 1) local += __shfl_xor_sync(~0u, local, o);
        if ((tid & 31) == 0) red[tid >> 5] = local;
        __syncthreads();
        if (tid == 0) {
            float s = 0.f;
#pragma unroll
            for (int i = 0; i < 8; i++) s += red[i];
            psum[tc * BB + b] = s;
        }
    }

    // 8 independent accumulators: deep FMA-chain break, high load MLP.
    const float* base = henc + (size_t)b * TT * DE + (size_t)tc * 512 * DE + e;
    float a0 = 0.f, a1 = 0.f, a2 = 0.f, a3 = 0.f, a4 = 0.f, a5 = 0.f, a6 = 0.f, a7 = 0.f;
#pragma unroll 2
    for (int t = 0; t < 512; t += 8) {
        a0 = fmaf(ws[t + 0], base[(size_t)(t + 0) * DE], a0);
        a1 = fmaf(ws[t + 1], base[(size_t)(t + 1) * DE], a1);
        a2 = fmaf(ws[t + 2], base[(size_t)(t + 2) * DE], a2);
        a3 = fmaf(ws[t + 3], base[(size_t)(t + 3) * DE], a3);
        a4 = fmaf(ws[t + 4], base[(size_t)(t + 4) * DE], a4);
        a5 = fmaf(ws[t + 5], base[(size_t)(t + 5) * DE], a5);
        a6 = fmaf(ws[t + 6], base[(size_t)(t + 6) * DE], a6);
        a7 = fmaf(ws[t + 7], base[(size_t)(t + 7) * DE], a7);
    }
    part[((size_t)tc * BB + b) * DE + e] = ((a0 + a1) + (a2 + a3)) + ((a4 + a5) + (a6 + a7));
}

// ---------------- kernel 5: finalize — normalize ctx and w ----------------
__global__ void finalize_kernel(const float* __restrict__ part, const float* __restrict__ psum,
                                float* __restrict__ ctx, float* __restrict__ w) {
    int b = blockIdx.x;
    int tid = threadIdx.x;  // 512
    __shared__ float invS;
    if (tid == 0) {
        float s = 0.f;
#pragma unroll
        for (int p = 0; p < 8; p++) s += psum[p * BB + b];
        invS = 1.f / s;
    }
    __syncthreads();
    float inv = invS;
    {
        float s = 0.f;
#pragma unroll
        for (int p = 0; p < 8; p++) s += part[((size_t)p * BB + b) * DE + tid];
        ctx[(size_t)b * DE + tid] = s * inv;
    }
    for (int t = tid; t < TT; t += 512)
        w[(size_t)b * TT + t] *= inv;
}

// ---------------- host launcher ----------------
extern "C" void kernel_launch(void* const* d_in, const int* in_sizes, int n_in,
                              void* d_out, int out_size) {
    const float* h_enc = (const float*)d_in[0];
    const float* h_dec = (const float*)d_in[1];
    const float* Wq_w  = (const float*)d_in[2];
    const float* Wq_b  = (const float*)d_in[3];
    const float* Wk_w  = (const float*)d_in[4];
    const float* Wk_b  = (const float*)d_in[5];
    const float* v_w   = (const float*)d_in[6];
    const void*  mask  = (const void*)d_in[7];

    float* out = (float*)d_out;
    float* ctx = out;                 // [B, 512]
    float* w   = out + BB * DE;       // [B, 4096]

    void *p_wk, *p_qpk, *p_sc, *p_part, *p_psum;
    cudaGetSymbolAddress(&p_wk, g_wk_bf);
    cudaGetSymbolAddress(&p_qpk, g_qpk);
    cudaGetSymbolAddress(&p_sc, g_scores);
    cudaGetSymbolAddress(&p_part, g_ctx_part);
    cudaGetSymbolAddress(&p_psum, g_psum);

    cudaFuncSetAttribute(gemm_score_kernel, cudaFuncAttributeMaxDynamicSharedMemorySize, GEMM_SMEM);

    convert_kernel<<<(DA * DE / 4) / 256, 256>>>(Wk_w, (__nv_bfloat16*)p_wk, DA * DE / 4);
    qpk_kernel<<<BB, 256>>>(h_dec, Wq_w, Wq_b, Wk_b, (float*)p_qpk);
    gemm_score_kernel<<<BB * 32, 512, GEMM_SMEM>>>(
        h_enc, (const __nv_bfloat16*)p_wk,
        (const float*)p_qpk, v_w, (float*)p_sc);
    ctx_part_kernel<<<dim3(2, BB, 8), 256>>>(h_enc, (const float*)p_sc, mask,
                                             w, (float*)p_part, (float*)p_psum);
    finalize_kernel<<<BB, 512>>>((const float*)p_part, (const float*)p_psum, ctx, w);
}

// round 17
// speedup vs baseline: 1.1665x; 1.1665x over previous
#include <cuda_runtime.h>
#include <cuda_bf16.h>
#include <cstdint>
#include <cstddef>

// Problem dims (fixed by the reference)
#define BB   64
#define TT   4096
#define DE   512
#define DA   256

// ---------------- scratch (device globals; no allocation in kernel_launch) ----------------
__device__ __nv_bfloat16 g_wk_bf[DA * DE];                  // 256 KB
__device__ float         g_qpk[BB * DA];                    // q + Wq_b + Wk_b
__device__ float         g_scores[(size_t)BB * TT];         // full additive scores
__device__ float         g_ctx_part[8][(size_t)BB * DE];    // T-split partial ctx
__device__ float         g_psum[8][BB];                     // T-split partial exp-sums

// ---------------- PTX helpers (compute_103-safe: no tcgen05/TMEM) ----------------
__device__ __forceinline__ uint32_t smem_u32(const void* p) {
    uint32_t a;
    asm("{ .reg .u64 t; cvta.to.shared.u64 t, %1; cvt.u32.u64 %0, t; }" : "=r"(a) : "l"(p));
    return a;
}
__device__ __forceinline__ void cp_async16(uint32_t dst, const void* src) {
    asm volatile("cp.async.cg.shared.global [%0], [%1], 16;" :: "r"(dst), "l"(src) : "memory");
}
__device__ __forceinline__ void cp_commit() {
    asm volatile("cp.async.commit_group;" ::: "memory");
}
template <int N>
__device__ __forceinline__ void cp_wait() {
    asm volatile("cp.async.wait_group %0;" :: "n"(N) : "memory");
}
__device__ __forceinline__ void ldmatrix_x4(uint32_t* r, uint32_t addr) {
    asm volatile("ldmatrix.sync.aligned.m8n8.x4.shared.b16 {%0,%1,%2,%3}, [%4];"
                 : "=r"(r[0]), "=r"(r[1]), "=r"(r[2]), "=r"(r[3]) : "r"(addr));
}
__device__ __forceinline__ void mma16816(float* c, const uint32_t* a, const uint32_t* b) {
    asm volatile(
        "mma.sync.aligned.m16n8k16.row.col.f32.bf16.bf16.f32 "
        "{%0,%1,%2,%3}, {%4,%5,%6,%7}, {%8,%9}, {%0,%1,%2,%3};"
        : "+f"(c[0]), "+f"(c[1]), "+f"(c[2]), "+f"(c[3])
        : "r"(a[0]), "r"(a[1]), "r"(a[2]), "r"(a[3]), "r"(b[0]), "r"(b[1]));
}
__device__ __forceinline__ float tanh_approx(float x) {
    float y;
    asm("tanh.approx.f32 %0, %1;" : "=f"(y) : "f"(x));
    return y;
}
__device__ __forceinline__ uint32_t pack_bf16x2(float lo, float hi) {
    __nv_bfloat162 p = __floats2bfloat162_rn(lo, hi);
    return *reinterpret_cast<uint32_t*>(&p);
}

// SW128 swizzle (Swizzle<3,4,3>) on tile-local byte offsets, rows = 128B.
#define SWZ(o) ((o) ^ (((o) >> 3) & 0x70))

// ---------------- kernel 1: f32 -> bf16 convert (Wk only) ----------------
__global__ void convert_kernel(const float* __restrict__ src, __nv_bfloat16* __restrict__ dst, long n4) {
    long i = (long)blockIdx.x * blockDim.x + threadIdx.x;
    if (i >= n4) return;
    float4 v = reinterpret_cast<const float4*>(src)[i];
    uint2 o;
    o.x = pack_bf16x2(v.x, v.y);
    o.y = pack_bf16x2(v.z, v.w);
    reinterpret_cast<uint2*>(dst)[i] = o;
}

// ---------------- kernel 2: qpk[b,a] = h_dec[b]·Wq[a] + Wq_b[a] + Wk_b[a] ----------------
__global__ void qpk_kernel(const float* __restrict__ hdec, const float* __restrict__ Wq,
                           const float* __restrict__ Wqb, const float* __restrict__ Wkb,
                           float* __restrict__ qpk) {
    int b = blockIdx.x;
    int a = threadIdx.x;  // 256
    __shared__ float h[DE];
    for (int e = threadIdx.x; e < DE; e += 256) h[e] = hdec[b * DE + e];
    __syncthreads();
    const float* w = Wq + (size_t)a * DE;
    float acc = 0.f;
#pragma unroll 8
    for (int e = 0; e < DE; e++) acc = fmaf(h[e], w[e], acc);
    qpk[b * DA + a] = acc + Wqb[a] + Wkb[a];
}

// ---------------- kernel 3: mma.sync GEMM (M=128,N=256), R12 structure, LSU-reduced ----------------
// 512 threads = 16 warps = 2(M) x 8(N). K=512 in 8 chunks of 64.
// A staging: per thread 2 (row,16B-unit) pairs -> 4 LDG.128 + 2 STS.128 (stores halved vs R12).
// B fragments: 2x ldmatrix.x4 per k-step (LDSM halved vs R12).
#define SM_PART   0                              // float s_part[8][128] = 4096 B
#define SM_V      4096                           // float sv[256]
#define SM_Q      5120                           // float sq[256]
#define SM_A(st)  (6144 + (st) * 16384)          // A stage: 128 rows x 128 B (bf16)
#define SM_B(st)  (38912 + (st) * 32768)         // B stage: 256 rows x 128 B (bf16)
#define GEMM_SMEM 104448

__global__ void __launch_bounds__(512, 1) gemm_score_kernel(
    const float* __restrict__ A,            // [B*T, 512] f32 (h_enc)
    const __nv_bfloat16* __restrict__ Bm,   // [256, 512] bf16 (Wk)
    const float* __restrict__ qpk,
    const float* __restrict__ v_w,
    float* __restrict__ scores) {           // [B*T]
    extern __shared__ char smem[];
    uint32_t sb = smem_u32(smem);
    int tid = threadIdx.x;
    int wid = tid >> 5, lane = tid & 31;
    int wm = wid >> 3, wn = wid & 7;
    int g = lane >> 2, tig = lane & 3;

    int bx = blockIdx.x;                   // b*32 + mt
    int b  = bx >> 5;
    int t0 = (bx & 31) << 7;
    size_t m0 = (size_t)bx * 128;

    if (tid < 256) {
        ((float*)(smem + SM_V))[tid] = v_w[tid];
        ((float*)(smem + SM_Q))[tid] = qpk[b * DA + tid];
    }

    const float* Abase = A + m0 * DE;

    // A staging geometry: chunk = 128 rows x 8 16B-units (bf16). 512 threads x 2 units.
    // unit (row, c8): f32 source = 32B at row*2048 + c8*32 (2 contiguous float4),
    // bf16 dest = 16B at SWZ(row*128 + c8*16)  -> one STS.128.
    int arowp = tid >> 3;                  // 0..63 (+64 for second unit)
    int ac8   = tid & 7;
    uint32_t aswp[2];
    aswp[0] = (uint32_t)SWZ(arowp * 128 + ac8 * 16);
    aswp[1] = (uint32_t)SWZ((arowp + 64) * 128 + ac8 * 16);

    auto ldgA = [&](int kc, float4* st) {
        const float4* src = (const float4*)(Abase + (size_t)kc * 64);
#pragma unroll
        for (int i = 0; i < 2; i++) {
            size_t base = (size_t)(arowp + i * 64) * 128 + ac8 * 2;
            st[2 * i + 0] = src[base + 0];
            st[2 * i + 1] = src[base + 1];
        }
    };
    auto stsA = [&](int stg, const float4* st) {
        char* dst = smem + SM_A(stg);
#pragma unroll
        for (int i = 0; i < 2; i++) {
            uint4 o;
            o.x = pack_bf16x2(st[2 * i + 0].x, st[2 * i + 0].y);
            o.y = pack_bf16x2(st[2 * i + 0].z, st[2 * i + 0].w);
            o.z = pack_bf16x2(st[2 * i + 1].x, st[2 * i + 1].y);
            o.w = pack_bf16x2(st[2 * i + 1].z, st[2 * i + 1].w);
            *reinterpret_cast<uint4*>(dst + aswp[i]) = o;
        }
    };
    // B chunk = 256 rows x 64 bf16 = 2048 x 16B; 512 threads x 4 each.
    auto issueB = [&](int kc, int stg) {
        uint32_t bS = sb + SM_B(stg);
        const __nv_bfloat16* bb = Bm + kc * 64;
#pragma unroll
        for (int i = 0; i < 4; i++) {
            int c = tid + i * 512;
            int row = c >> 3, cc = c & 7;
            cp_async16(bS + SWZ(row * 128 + cc * 16), bb + (size_t)row * DE + cc * 8);
        }
        cp_commit();
    };

    float acc[4][4][4];
#pragma unroll
    for (int mi = 0; mi < 4; mi++)
#pragma unroll
        for (int ni = 0; ni < 4; ni++)
#pragma unroll
            for (int e = 0; e < 4; e++) acc[mi][ni][e] = 0.f;

    // ldmatrix per-lane selectors
    int arow = wm * 64 + (lane & 15);
    int acb  = lane >> 4;
    // B x4: lanes 0-7 -> n-subtile 0 khalf0, 8-15 -> khalf1, 16-23 -> subtile 1 khalf0, 24-31 -> khalf1
    int browx = wn * 32 + ((lane >> 4) << 3) + (lane & 7);   // + ni2*16
    int bkbx  = ((lane >> 3) & 1) * 16;

    // ---- prologue: stage 0 staged ----
    {
        issueB(0, 0);
        float4 st[4];
        ldgA(0, st);
        stsA(0, st);
    }

#pragma unroll 1
    for (int kc = 0; kc < 8; kc++) {
        int cur = kc & 1, nxt = cur ^ 1;
        float4 st[4];
        if (kc < 7) ldgA(kc + 1, st);     // register-only; hoisted before wait
        cp_wait<0>();                      // drain B(cur)
        __syncthreads();                   // publish A/B(cur); reads of nxt retired
        if (kc < 7) issueB(kc + 1, nxt);   // safe post-sync

        uint32_t aS = sb + SM_A(cur), bS = sb + SM_B(cur);
#pragma unroll
        for (int ks = 0; ks < 4; ks++) {
            uint32_t af[4][4], bf_[4][2];
#pragma unroll
            for (int mi = 0; mi < 4; mi++)
                ldmatrix_x4(af[mi], aS + SWZ((arow + mi * 16) * 128 + ks * 32 + acb * 16));
#pragma unroll
            for (int ni2 = 0; ni2 < 2; ni2++) {
                uint32_t r4[4];
                ldmatrix_x4(r4, bS + SWZ((browx + ni2 * 16) * 128 + ks * 32 + bkbx));
                bf_[ni2 * 2 + 0][0] = r4[0];
                bf_[ni2 * 2 + 0][1] = r4[1];
                bf_[ni2 * 2 + 1][0] = r4[2];
                bf_[ni2 * 2 + 1][1] = r4[3];
            }
#pragma unroll
            for (int mi = 0; mi < 4; mi++)
#pragma unroll
                for (int ni = 0; ni < 4; ni++)
                    mma16816(acc[mi][ni], af[mi], bf_[ni]);
        }
        if (kc < 7)
            stsA(nxt, st);                 // 2x STS.128; published by next iteration's sync
    }
    __syncthreads();                        // retire MMA smem reads before s_part reuse

    // ---- epilogue: score = sum over all 256 a of v*tanh(qpk + k) ----
    const float* sv = (const float*)(smem + SM_V);
    const float* sq = (const float*)(smem + SM_Q);
    float* s_part = (float*)(smem + SM_PART);

#pragma unroll
    for (int mi = 0; mi < 4; mi++) {
        float plo = 0.f, phi = 0.f;
#pragma unroll
        for (int ni = 0; ni < 4; ni++) {
            int n = wn * 32 + ni * 8 + tig * 2;
            float v0 = sv[n], v1 = sv[n + 1], q0 = sq[n], q1 = sq[n + 1];
            plo = fmaf(v0, tanh_approx(q0 + acc[mi][ni][0]), plo);
            plo = fmaf(v1, tanh_approx(q1 + acc[mi][ni][1]), plo);
            phi = fmaf(v0, tanh_approx(q0 + acc[mi][ni][2]), phi);
            phi = fmaf(v1, tanh_approx(q1 + acc[mi][ni][3]), phi);
        }
        plo += __shfl_xor_sync(~0u, plo, 1);
        plo += __shfl_xor_sync(~0u, plo, 2);
        phi += __shfl_xor_sync(~0u, phi, 1);
        phi += __shfl_xor_sync(~0u, phi, 2);
        if (tig == 0) {
            int row = wm * 64 + mi * 16 + g;
            s_part[wn * 128 + row] = plo;
            s_part[wn * 128 + row + 8] = phi;
        }
    }
    __syncthreads();
    if (tid < 128) {
        float s = 0.f;
#pragma unroll
        for (int j = 0; j < 8; j++) s += s_part[j * 128 + tid];
        scores[(size_t)b * TT + t0 + tid] = s;
    }
}

// ---------------- kernel 4: fused exp/mask + partial ctx over T-chunks (R12 version) ----------------
// grid (2, BB, 8): block covers 256 e-columns x 512 timesteps.
__global__ void ctx_part_kernel(const float* __restrict__ henc, const float* __restrict__ sc,
                                const void* __restrict__ maskp,
                                float* __restrict__ w, float* __restrict__ part,
                                float* __restrict__ psum) {
    int b = blockIdx.y;
    int tc = blockIdx.z;
    int e = blockIdx.x * 256 + threadIdx.x;
    int tid = threadIdx.x;
    __shared__ float ws[512];
    __shared__ float red[8];
    __shared__ int is_i32_sh;

    if (tid == 0) {
        // mask dtype auto-detect: int32 0/1 vs 1-byte bool (see R5 note)
        const uint32_t* mw = (const uint32_t*)maskp;
        int ok = 1;
        for (int i = 0; i < 64; i++)
            if (mw[i] > 1u) { ok = 0; break; }
        is_i32_sh = ok;
    }
    __syncthreads();
    int is_i32 = is_i32_sh;
    const int* mi32 = (const int*)maskp;
    const unsigned char* mu8 = (const unsigned char*)maskp;

    const float* s0 = sc + (size_t)b * TT + tc * 512;
    float local = 0.f;
    for (int t = tid; t < 512; t += 256) {
        size_t idx = (size_t)b * TT + tc * 512 + t;
        bool mv = is_i32 ? (mi32[idx] != 0) : (mu8[idx] != 0);
        float p = mv ? __expf(s0[t]) : 0.f;
        ws[t] = p;
        local += p;
    }
    __syncthreads();

    if (blockIdx.x == 0) {
        for (int t = tid; t < 512; t += 256) w[(size_t)b * TT + tc * 512 + t] = ws[t];
#pragma unroll
        for (int o = 16; o; o >>= 1) local += __shfl_xor_sync(~0u, local, o);
        if ((tid & 31) == 0) red[tid >> 5] = local;
        __syncthreads();
        if (tid == 0) {
            float s = 0.f;
#pragma unroll
            for (int i = 0; i < 8; i++) s += red[i];
            psum[tc * BB + b] = s;
        }
    }

    // 8 independent accumulators: deep FMA-chain break, high load MLP.
    const float* base = henc + (size_t)b * TT * DE + (size_t)tc * 512 * DE + e;
    float a0 = 0.f, a1 = 0.f, a2 = 0.f, a3 = 0.f, a4 = 0.f, a5 = 0.f, a6 = 0.f, a7 = 0.f;
#pragma unroll 2
    for (int t = 0; t < 512; t += 8) {
        a0 = fmaf(ws[t + 0], base[(size_t)(t + 0) * DE], a0);
        a1 = fmaf(ws[t + 1], base[(size_t)(t + 1) * DE], a1);
        a2 = fmaf(ws[t + 2], base[(size_t)(t + 2) * DE], a2);
        a3 = fmaf(ws[t + 3], base[(size_t)(t + 3) * DE], a3);
        a4 = fmaf(ws[t + 4], base[(size_t)(t + 4) * DE], a4);
        a5 = fmaf(ws[t + 5], base[(size_t)(t + 5) * DE], a5);
        a6 = fmaf(ws[t + 6], base[(size_t)(t + 6) * DE], a6);
        a7 = fmaf(ws[t + 7], base[(size_t)(t + 7) * DE], a7);
    }
    part[((size_t)tc * BB + b) * DE + e] = ((a0 + a1) + (a2 + a3)) + ((a4 + a5) + (a6 + a7));
}

// ---------------- kernel 5: finalize — normalize ctx and w ----------------
__global__ void finalize_kernel(const float* __restrict__ part, const float* __restrict__ psum,
                                float* __restrict__ ctx, float* __restrict__ w) {
    int b = blockIdx.x;
    int tid = threadIdx.x;  // 512
    __shared__ float invS;
    if (tid == 0) {
        float s = 0.f;
#pragma unroll
        for (int p = 0; p < 8; p++) s += psum[p * BB + b];
        invS = 1.f / s;
    }
    __syncthreads();
    float inv = invS;
    {
        float s = 0.f;
#pragma unroll
        for (int p = 0; p < 8; p++) s += part[((size_t)p * BB + b) * DE + tid];
        ctx[(size_t)b * DE + tid] = s * inv;
    }
    for (int t = tid; t < TT; t += 512)
        w[(size_t)b * TT + t] *= inv;
}

// ---------------- host launcher ----------------
extern "C" void kernel_launch(void* const* d_in, const int* in_sizes, int n_in,
                              void* d_out, int out_size) {
    const float* h_enc = (const float*)d_in[0];
    const float* h_dec = (const float*)d_in[1];
    const float* Wq_w  = (const float*)d_in[2];
    const float* Wq_b  = (const float*)d_in[3];
    const float* Wk_w  = (const float*)d_in[4];
    const float* Wk_b  = (const float*)d_in[5];
    const float* v_w   = (const float*)d_in[6];
    const void*  mask  = (const void*)d_in[7];

    float* out = (float*)d_out;
    float* ctx = out;                 // [B, 512]
    float* w   = out + BB * DE;       // [B, 4096]

    void *p_wk, *p_qpk, *p_sc, *p_part, *p_psum;
    cudaGetSymbolAddress(&p_wk, g_wk_bf);
    cudaGetSymbolAddress(&p_qpk, g_qpk);
    cudaGetSymbolAddress(&p_sc, g_scores);
    cudaGetSymbolAddress(&p_part, g_ctx_part);
    cudaGetSymbolAddress(&p_psum, g_psum);

    cudaFuncSetAttribute(gemm_score_kernel, cudaFuncAttributeMaxDynamicSharedMemorySize, GEMM_SMEM);

    convert_kernel<<<(DA * DE / 4) / 256, 256>>>(Wk_w, (__nv_bfloat16*)p_wk, DA * DE / 4);
    qpk_kernel<<<BB, 256>>>(h_dec, Wq_w, Wq_b, Wk_b, (float*)p_qpk);
    gemm_score_kernel<<<BB * 32, 512, GEMM_SMEM>>>(
        h_enc, (const __nv_bfloat16*)p_wk,
        (const float*)p_qpk, v_w, (float*)p_sc);
    ctx_part_kernel<<<dim3(2, BB, 8), 256>>>(h_enc, (const float*)p_sc, mask,
                                             w, (float*)p_part, (float*)p_psum);
    finalize_kernel<<<BB, 512>>>((const float*)p_part, (const float*)p_psum, ctx, w);
}